// round 12
// baseline (speedup 1.0000x reference)
#include <cuda_runtime.h>
#include <cuda_fp16.h>
#include <cstdint>
#include <math.h>

#define T_STEPS 512
#define BATCH   64
#define IN_DIM  1024
#define HID     1024
#define GATES   4096
#define NCTA    128
#define M_TOT   (T_STEPS * BATCH)      // 32768

// ---------------- static scratch ----------------
__device__ __half g_Xh[(size_t)M_TOT * IN_DIM];            // 64 MB (fp16 x)
__device__ __half g_Wth[(size_t)GATES * IN_DIM];           // 8 MB  [n][k] fp16
__device__ float    g_xw[(size_t)T_STEPS * BATCH * GATES]; // 512 MB, layout [t][b][j][gate]
__device__ uint32_t g_hfrag[(size_t)T_STEPS * 32768];      // 64 MB (h fp16, mma A-frag layout)
__device__ int      g_flags[2048];                         // [mt][t] : mt*512 + t

// ---------------- helpers ----------------
__device__ __forceinline__ uint32_t pack2h(__half a, __half b) {
    __half2 t = __halves2half2(a, b);
    return *reinterpret_cast<uint32_t*>(&t);
}
__device__ __forceinline__ void mma16816h(float* c, const uint32_t* a, const uint32_t* b) {
    asm volatile(
        "mma.sync.aligned.m16n8k16.row.col.f32.f16.f16.f32 "
        "{%0,%1,%2,%3}, {%4,%5,%6,%7}, {%8,%9}, {%0,%1,%2,%3};\n"
        : "+f"(c[0]), "+f"(c[1]), "+f"(c[2]), "+f"(c[3])
        : "r"(a[0]), "r"(a[1]), "r"(a[2]), "r"(a[3]), "r"(b[0]), "r"(b[1]));
}
__device__ __forceinline__ void ldsm_x4(uint32_t* r, uint32_t saddr) {
    asm volatile("ldmatrix.sync.aligned.m8n8.x4.shared.b16 {%0,%1,%2,%3}, [%4];\n"
        : "=r"(r[0]), "=r"(r[1]), "=r"(r[2]), "=r"(r[3]) : "r"(saddr));
}
__device__ __forceinline__ void cpasync16(uint32_t s, const void* g) {
    asm volatile("cp.async.cg.shared.global [%0], [%1], 16;\n" :: "r"(s), "l"(g));
}
#define CP_COMMIT() asm volatile("cp.async.commit_group;\n")
#define CP_WAIT1()  asm volatile("cp.async.wait_group 1;\n")

__device__ __forceinline__ void flag_release_add(int* p) {
    asm volatile("red.release.gpu.global.add.s32 [%0], %1;" :: "l"(p), "r"(1) : "memory");
}
__device__ __forceinline__ int flag_acquire_ld(const int* p) {
    int v;
    asm volatile("ld.acquire.gpu.global.s32 %0, [%1];" : "=r"(v) : "l"(p) : "memory");
    return v;
}

// =====================================================================
// Converters
// =====================================================================
__global__ __launch_bounds__(256)
void convert_x_kernel(const float* __restrict__ X)
{
    if (blockIdx.x == 0 && threadIdx.x < 256) {
        #pragma unroll
        for (int i = 0; i < 8; i++) g_flags[threadIdx.x + 256 * i] = 0;
    }
    size_t idx = (size_t)blockIdx.x * 256 + threadIdx.x;   // float4 index
    float4 v = ((const float4*)X)[idx];
    uint2 o;
    o.x = pack2h(__float2half(v.x), __float2half(v.y));
    o.y = pack2h(__float2half(v.z), __float2half(v.w));
    ((uint2*)g_Xh)[idx] = o;
}

__global__ __launch_bounds__(256)
void convert_w_kernel(const float* __restrict__ W)   // [k][n] fp32 -> [n][k] fp16
{
    __shared__ float st[32][33];
    const int n0 = blockIdx.x * 32;
    const int k0 = blockIdx.y * 32;
    const int tid = threadIdx.x;
    #pragma unroll
    for (int i = 0; i < 4; i++) {
        int id = tid + 256 * i;
        int kr = id >> 5, nc = id & 31;
        st[kr][nc] = W[(size_t)(k0 + kr) * GATES + n0 + nc];
    }
    __syncthreads();
    #pragma unroll
    for (int i = 0; i < 2; i++) {
        int id = tid + 256 * i;
        int nr = id >> 4, kc = id & 15;
        float v0 = st[2 * kc][nr], v1 = st[2 * kc + 1][nr];
        size_t o = (size_t)(n0 + nr) * (IN_DIM / 2) + (k0 >> 1) + kc;
        ((uint32_t*)g_Wth)[o] = pack2h(__float2half(v0), __float2half(v1));
    }
}

// =====================================================================
// Phase A: xw = x_f16 @ W_f16 + b.  Epilogue writes gate-packed layout:
// g_xw[row*4096 + j*4 + gate]   (j = col & 1023, gate = col >> 10)
// =====================================================================
#define STG_BYTES 30720
#define OFF_BHI   10240
#define PITCH     40

__global__ __launch_bounds__(256, 1)
void xw_gemm_kernel(const float* __restrict__ bias)
{
    extern __shared__ char sm[];
    const uint32_t smu = (uint32_t)__cvta_generic_to_shared(sm);

    const int tid  = threadIdx.x;
    const int lane = tid & 31;
    const int warp = tid >> 5;
    const int g    = lane >> 2;
    const int tg   = lane & 3;
    const int wm   = (warp & 3) * 32;
    const int wn   = (warp >> 2) * 128;
    const size_t m0 = (size_t)blockIdx.y * 128;
    const int    n0 = blockIdx.x * 256;

    const int rA = (lane & 7) | (((lane >> 3) & 1) << 3);
    const int cA = (lane >> 4) * 8;

    float acc[2][16][4];
    #pragma unroll
    for (int a = 0; a < 2; a++)
        #pragma unroll
        for (int b2 = 0; b2 < 16; b2++)
            #pragma unroll
            for (int c = 0; c < 4; c++) acc[a][b2][c] = 0.f;

    auto load_stage = [&](int s, int kk) {
        const int k0 = kk * 32;
        const uint32_t base = smu + s * STG_BYTES;
        #pragma unroll
        for (int i = 0; i < 2; i++) {
            int id  = tid + 256 * i;
            int row = id >> 2, ch = id & 3;
            const __half* src = g_Xh + (m0 + row) * (size_t)IN_DIM + k0 + ch * 8;
            cpasync16(base + (row * PITCH + ch * 8) * 2, src);
        }
        #pragma unroll
        for (int i = 0; i < 4; i++) {
            int id  = tid + 256 * i;
            int row = id >> 2, ch = id & 3;
            const __half* src = g_Wth + (size_t)(n0 + row) * IN_DIM + k0 + ch * 8;
            cpasync16(base + OFF_BHI + (row * PITCH + ch * 8) * 2, src);
        }
        CP_COMMIT();
    };

    load_stage(0, 0);
    load_stage(1, 1);

    for (int it = 0; it < 32; ++it) {
        CP_WAIT1();
        __syncthreads();
        if (it + 2 < 32) load_stage((it + 2) % 3, it + 2);
        else CP_COMMIT();

        const uint32_t sb = smu + (it % 3) * STG_BYTES;

        #pragma unroll
        for (int ks = 0; ks < 2; ks++) {
            uint32_t ah[2][4];
            #pragma unroll
            for (int mt = 0; mt < 2; mt++) {
                uint32_t ao = ((wm + mt * 16 + rA) * PITCH + ks * 16 + cA) * 2;
                ldsm_x4(ah[mt], sb + ao);
            }
            #pragma unroll
            for (int q = 0; q < 8; q++) {
                uint32_t bh[4];
                uint32_t bo = ((wn + q * 16 + rA) * PITCH + ks * 16 + cA) * 2;
                ldsm_x4(bh, sb + OFF_BHI + bo);
                uint32_t b0h[2] = {bh[0], bh[2]};
                uint32_t b1h[2] = {bh[1], bh[3]};
                #pragma unroll
                for (int mt = 0; mt < 2; mt++) {
                    mma16816h(acc[mt][2*q],   ah[mt], b0h);
                    mma16816h(acc[mt][2*q+1], ah[mt], b1h);
                }
            }
        }
    }

    // epilogue: gate-packed scatter  g_xw[row*4096 + j*4 + gate]
    #pragma unroll
    for (int mt = 0; mt < 2; mt++) {
        #pragma unroll
        for (int nt = 0; nt < 16; nt++) {
            size_t row = m0 + wm + mt * 16 + g;
            int    col = n0 + wn + nt * 8 + 2 * tg;
            int gate = col >> 10;
            int j    = col & 1023;
            float b0 = bias[col], b1 = bias[col + 1];
            size_t a0 = row * GATES + (size_t)j * 4 + gate;
            g_xw[a0]               = acc[mt][nt][0] + b0;
            g_xw[a0 + 4]           = acc[mt][nt][1] + b1;
            g_xw[a0 + 8 * GATES]     = acc[mt][nt][2] + b0;
            g_xw[a0 + 8 * GATES + 4] = acc[mt][nt][3] + b1;
        }
    }
}

// =====================================================================
// Phase B v8: v7 + per-mt flag pipelines (no CTA barrier in loop) +
// gate-packed xw loads (2x LDG.128 per lane).
// Warp = (mt = w&3, nh = w>>2), full K=1024. Flag[mt][t] target = 256
// (2 nh-warps x 128 CTAs); consumers with m-tile mt read only mt frags.
// =====================================================================
#define WS_PITCH 520      // u32 per W column (520 % 32 == 8 -> conflict-free)

__global__ __launch_bounds__(256, 1)
void lstm_rec_kernel(const float* __restrict__ Wh, float* __restrict__ out,
                     int write_tail)
{
    extern __shared__ char smraw[];
    uint32_t* Wsf = (uint32_t*)smraw;                 // 32*520 u32 = 66560 B

    const int tid  = threadIdx.x;
    const int lane = tid & 31;
    const int warp = tid >> 5;
    const int g    = lane >> 2;
    const int tg   = lane & 3;
    const int mt   = warp & 3;        // m-tile (16 batch rows)
    const int nh   = warp >> 2;       // j-group (4 hidden cols)
    const int wm   = mt * 16;
    const int j0   = blockIdx.x * 8;

    // one-time: W_h slice -> SMEM fragment layout, REORDERED columns:
    // smem col c: nh=c>>4, q=(c>>3)&1, cc=c&7; gate=2q+(cc&1), jj=nh*4+(cc>>1)
    for (int i = tid; i < 32 * 1024; i += 256) {
        int c = i & 31;
        int k = i >> 5;
        int nhc = c >> 4, qc = (c >> 3) & 1, cc = c & 7;
        int gate = 2 * qc + (cc & 1);
        int jj   = nhc * 4 + (cc >> 1);
        float v = Wh[(size_t)k * GATES + gate * HID + j0 + jj];
        int kt = k >> 4, t4 = (k >> 1) & 3, w = (k >> 3) & 1, hf = k & 1;
        int word = c * WS_PITCH + kt * 8 + t4 * 2 + w;
        ((__half*)Wsf)[word * 2 + hf] = __float2half(v);
    }
    __syncthreads();

    const int r0 = wm + g;            // batch rows this lane owns
    const int r1 = wm + g + 8;
    const int j  = j0 + nh * 4 + tg;  // the single hidden col this lane owns

    int* my_flags = g_flags + mt * 512;   // per-mt pipeline flags

    float creg[2] = {0.f, 0.f};       // c for (r0,j), (r1,j)

    for (int t = 0; t < T_STEPS; t++) {
        // ---- xw prefetch, gate-packed: 2 x LDG.128 (independent of spin) ----
        const float* xwt = g_xw + (size_t)t * BATCH * GATES;
        float4 x0 = *(const float4*)(xwt + (size_t)r0 * GATES + (size_t)j * 4);
        float4 x1 = *(const float4*)(xwt + (size_t)r1 * GATES + (size_t)j * 4);

        // parity-split accumulators: [parity][q][4]
        float acc[2][2][4];
        #pragma unroll
        for (int pp = 0; pp < 2; pp++)
            #pragma unroll
            for (int q = 0; q < 2; q++)
                #pragma unroll
                for (int c2 = 0; c2 < 4; c2++) acc[pp][q][c2] = 0.f;

        if (t > 0) {
            // per-warp acquire spin on this mt-pipeline's flag
            if (lane == 0) {
                while (flag_acquire_ld(my_flags + (t - 1)) != 256) { }
            }
            __syncwarp();

            const uint32_t* ab = g_hfrag + (size_t)(t - 1) * 32768
                                 + mt * 128 + lane * 4;

            // 8-deep prefetch ring
            uint4 H[8];
            #pragma unroll
            for (int q = 0; q < 8; q++) H[q] = *(const uint4*)(ab + q * 512);

            #pragma unroll 8
            for (int kt = 0; kt < 64; kt++) {
                int s = kt & 7;
                uint32_t ah[4] = {H[s].x, H[s].y, H[s].z, H[s].w};
                float* a0 = acc[kt & 1][0];
                float* a1 = acc[kt & 1][1];
                {
                    int c = nh * 16 + g;
                    uint2 bf = *(const uint2*)(Wsf + c * WS_PITCH + kt * 8 + tg * 2);
                    uint32_t bh[2] = {bf.x, bf.y};
                    mma16816h(a0, ah, bh);
                }
                {
                    int c = nh * 16 + 8 + g;
                    uint2 bf = *(const uint2*)(Wsf + c * WS_PITCH + kt * 8 + tg * 2);
                    uint32_t bh[2] = {bf.x, bf.y};
                    mma16816h(a1, ah, bh);
                }
                if (kt + 8 < 64) H[s] = *(const uint4*)(ab + (kt + 8) * 512);
            }
        }

        // ---- fold parity halves; in-register activations ----
        float hn[2], cn[2];
        #pragma unroll
        for (int rr = 0; rr < 2; rr++) {
            float xi = rr ? x1.x : x0.x;
            float xf = rr ? x1.y : x0.y;
            float xG = rr ? x1.z : x0.z;
            float xo = rr ? x1.w : x0.w;
            float gi = acc[0][0][2 * rr + 0] + acc[1][0][2 * rr + 0] + xi;
            float gf = acc[0][0][2 * rr + 1] + acc[1][0][2 * rr + 1] + xf;
            float gg = acc[0][1][2 * rr + 0] + acc[1][1][2 * rr + 0] + xG;
            float go = acc[0][1][2 * rr + 1] + acc[1][1][2 * rr + 1] + xo;
            float iv = 1.f / (1.f + expf(-gi));
            float fv = 1.f / (1.f + expf(-gf));
            float gv = tanhf(gg);
            float ov = 1.f / (1.f + expf(-go));
            float c_ = fv * creg[rr] + iv * gv;
            float h_ = ov * tanhf(c_);
            creg[rr] = c_;
            cn[rr] = c_; hn[rr] = h_;
        }

        // ---- publish h fragments: pair j (even tg) with j+1 (odd tg) ----
        {
            uint32_t packed = pack2h(__float2half(hn[0]), __float2half(hn[1]));
            uint32_t nb = __shfl_xor_sync(0xffffffffu, packed, 1);
            if ((tg & 1) == 0) {
                uint32_t f0 = (packed & 0xffffu) | (nb << 16);       // row r0
                uint32_t f1 = (packed >> 16) | (nb & 0xffff0000u);   // row r1
                int kk = j & 15, kt = j >> 4;
                int fl = g * 4 + ((kk >> 1) & 3);
                int rg0 = (kk >> 3) << 1;
                size_t fb = (size_t)t * 32768 + (size_t)kt * 512 + mt * 128 + fl * 4 + rg0;
                *(uint2*)(g_hfrag + fb) = make_uint2(f0, f1);
            }
        }

        // ---- per-warp release (no CTA barrier) ----
        __syncwarp();
        if (lane == 0) flag_release_add(my_flags + t);

        // ---- off-critical-path output stores ----
        float* hdst = out + (size_t)t * BATCH * HID;
        hdst[(size_t)r0 * HID + j] = hn[0];
        hdst[(size_t)r1 * HID + j] = hn[1];
        if (t == T_STEPS - 1 && write_tail) {
            size_t base = (size_t)T_STEPS * BATCH * HID;
            out[base + (size_t)r0 * HID + j] = hn[0];
            out[base + (size_t)r1 * HID + j] = hn[1];
            out[base + BATCH * HID + (size_t)r0 * HID + j] = cn[0];
            out[base + BATCH * HID + (size_t)r1 * HID + j] = cn[1];
        }
    }
}

// =====================================================================
extern "C" void kernel_launch(void* const* d_in, const int* in_sizes, int n_in,
                              void* d_out, int out_size)
{
    const float* x  = (const float*)d_in[0];
    const float* Wx = (const float*)d_in[1];
    const float* Wh = (const float*)d_in[2];
    const float* b  = (const float*)d_in[3];
    float* out = (float*)d_out;

    convert_x_kernel<<<(M_TOT * IN_DIM / 4) / 256, 256>>>(x);
    convert_w_kernel<<<dim3(GATES / 32, IN_DIM / 32), 256>>>(Wx);

    const int smemA = 3 * STG_BYTES;
    cudaFuncSetAttribute(xw_gemm_kernel,
                         cudaFuncAttributeMaxDynamicSharedMemorySize, smemA);
    dim3 gridA(GATES / 256, M_TOT / 128);
    xw_gemm_kernel<<<gridA, 256, smemA>>>(b);

    const int smemB = 32 * WS_PITCH * 4;   // 66560
    cudaFuncSetAttribute(lstm_rec_kernel,
                         cudaFuncAttributeMaxDynamicSharedMemorySize, smemB);
    int write_tail = (out_size > T_STEPS * BATCH * HID) ? 1 : 0;
    lstm_rec_kernel<<<NCTA, 256, smemB>>>(Wh, out, write_tail);
}

// round 13
// speedup vs baseline: 1.3185x; 1.3185x over previous
#include <cuda_runtime.h>
#include <cuda_fp16.h>
#include <cstdint>
#include <math.h>

#define T_STEPS 512
#define BATCH   64
#define IN_DIM  1024
#define HID     1024
#define GATES   4096
#define NCTA    128

// ---------------- static scratch ----------------
__device__ uint32_t g_xfrag[(size_t)T_STEPS * 32768];   // 64 MB: x fp16, mma A-frag layout
__device__ uint32_t g_hfrag[(size_t)T_STEPS * 32768];   // 64 MB: h fp16, mma A-frag layout
__device__ int      g_flags[T_STEPS];

// ---------------- helpers ----------------
__device__ __forceinline__ uint32_t pack2h(__half a, __half b) {
    __half2 t = __halves2half2(a, b);
    return *reinterpret_cast<uint32_t*>(&t);
}
__device__ __forceinline__ void mma16816h(float* c, const uint32_t* a, const uint32_t* b) {
    asm volatile(
        "mma.sync.aligned.m16n8k16.row.col.f32.f16.f16.f32 "
        "{%0,%1,%2,%3}, {%4,%5,%6,%7}, {%8,%9}, {%0,%1,%2,%3};\n"
        : "+f"(c[0]), "+f"(c[1]), "+f"(c[2]), "+f"(c[3])
        : "r"(a[0]), "r"(a[1]), "r"(a[2]), "r"(a[3]), "r"(b[0]), "r"(b[1]));
}
__device__ __forceinline__ void flag_release_add(int* p) {
    asm volatile("red.release.gpu.global.add.s32 [%0], %1;" :: "l"(p), "r"(1) : "memory");
}
__device__ __forceinline__ int flag_acquire_ld(const int* p) {
    int v;
    asm volatile("ld.acquire.gpu.global.s32 %0, [%1];" : "=r"(v) : "l"(p) : "memory");
    return v;
}
#define BAR_SYNC(id, cnt)   asm volatile("bar.sync %0, %1;"   :: "r"(id), "r"(cnt) : "memory")
#define BAR_ARRIVE(id, cnt) asm volatile("bar.arrive %0, %1;" :: "r"(id), "r"(cnt) : "memory")
// barrier ids
#define BFULL0  1
#define BEMPTY0 3
#define BREC    5

// =====================================================================
// Converter: x fp32 -> fp16 mma A-fragment layout (R8-proven).
// grid (64 kt, 512 t), block 128 (warp = mt, lane = fl).
// =====================================================================
__global__ __launch_bounds__(128)
void convert_x_kernel(const float* __restrict__ X)
{
    if (blockIdx.x == 0 && blockIdx.y == 0) {
        #pragma unroll
        for (int i = 0; i < 4; i++) g_flags[threadIdx.x + 128 * i] = 0;
    }
    const int kt = blockIdx.x;
    const int t  = blockIdx.y;
    const int mt = threadIdx.x >> 5;
    const int fl = threadIdx.x & 31;
    const int g  = fl >> 2;
    const int tg = fl & 3;
    const int bb = mt * 16 + g;
    const int k  = kt * 16 + tg * 2;

    const float* xt = X + (size_t)t * BATCH * IN_DIM;
    float2 r00 = *(const float2*)(xt + (size_t)bb * IN_DIM + k);
    float2 r10 = *(const float2*)(xt + (size_t)(bb + 8) * IN_DIM + k);
    float2 r01 = *(const float2*)(xt + (size_t)bb * IN_DIM + k + 8);
    float2 r11 = *(const float2*)(xt + (size_t)(bb + 8) * IN_DIM + k + 8);
    uint4 o;
    o.x = pack2h(__float2half(r00.x), __float2half(r00.y));
    o.y = pack2h(__float2half(r10.x), __float2half(r10.y));
    o.z = pack2h(__float2half(r01.x), __float2half(r01.y));
    o.w = pack2h(__float2half(r11.x), __float2half(r11.y));
    *(uint4*)(g_xfrag + (size_t)t * 32768 + kt * 512 + mt * 128 + fl * 4) = o;
}

// =====================================================================
// Fused persistent LSTM: 384 threads.
//   warps 0-7  : recurrence (v7 structure: mt = w&3, nh = w>>2, full K,
//                8-deep ring, parity accs, in-register act)
//   warps 8-11 : xw producers (mt = w-8, all 32 gate cols, x-frags @ Wx)
// Handoff: SMEM ping-pong xwbuf[2], named barriers FULL/EMPTY (384),
// rec-only barrier BREC (256) before the global flag release.
// =====================================================================
#define WS_PITCH 520      // u32 per W column (520 % 32 == 8 -> conflict-free)
#define XWB_STRIDE 36     // floats per row (16B-aligned, conflict-spread)
#define XWB_SIZE  (64 * XWB_STRIDE)

__global__ __launch_bounds__(384, 1)
void lstm_fused_kernel(const float* __restrict__ Wx,
                       const float* __restrict__ Wh,
                       const float* __restrict__ b,
                       float* __restrict__ out,
                       int write_tail)
{
    extern __shared__ char smraw[];
    uint32_t* Whs  = (uint32_t*)smraw;                  // 32*520 u32 = 66560 B
    uint32_t* Wxs  = Whs + 32 * WS_PITCH;               // 66560 B
    float*    xwb  = (float*)(Wxs + 32 * WS_PITCH);     // 2 * 64*36 floats = 18432 B

    const int tid  = threadIdx.x;
    const int lane = tid & 31;
    const int warp = tid >> 5;
    const int g    = lane >> 2;
    const int tg   = lane & 3;
    const int j0   = blockIdx.x * 8;

    // ---- one-time: Wh & Wx slices -> SMEM fragment layout (reordered cols:
    // c: nh=c>>4, q=(c>>3)&1, cc=c&7; gate=2q+(cc&1), jj=nh*4+(cc>>1)) ----
    for (int i = tid; i < 32 * 1024; i += 384) {
        int c = i & 31;
        int k = i >> 5;
        int nhc = c >> 4, qc = (c >> 3) & 1, cc = c & 7;
        int gate = 2 * qc + (cc & 1);
        int jj   = nhc * 4 + (cc >> 1);
        size_t src = (size_t)k * GATES + gate * HID + j0 + jj;
        int kt = k >> 4, t4 = (k >> 1) & 3, w = (k >> 3) & 1, hf = k & 1;
        int word = c * WS_PITCH + kt * 8 + t4 * 2 + w;
        ((__half*)Whs)[word * 2 + hf] = __float2half(Wh[src]);
        ((__half*)Wxs)[word * 2 + hf] = __float2half(Wx[src]);
    }
    __syncthreads();

    if (warp < 8) {
        // ================== RECURRENCE WARPS ==================
        const int mt = warp & 3;
        const int nh = warp >> 2;
        const int wm = mt * 16;
        const int r0 = wm + g;
        const int r1 = wm + g + 8;
        const int j  = j0 + nh * 4 + tg;

        float creg[2] = {0.f, 0.f};

        for (int t = 0; t < T_STEPS; t++) {
            float acc[2][2][4];
            #pragma unroll
            for (int pp = 0; pp < 2; pp++)
                #pragma unroll
                for (int q = 0; q < 2; q++)
                    #pragma unroll
                    for (int c2 = 0; c2 < 4; c2++) acc[pp][q][c2] = 0.f;

            if (t > 0) {
                if (lane == 0) {
                    while (flag_acquire_ld(g_flags + (t - 1)) != NCTA) { }
                }
                __syncwarp();

                const uint32_t* ab = g_hfrag + (size_t)(t - 1) * 32768
                                     + mt * 128 + lane * 4;
                uint4 H[8];
                #pragma unroll
                for (int q = 0; q < 8; q++) H[q] = *(const uint4*)(ab + q * 512);

                #pragma unroll 8
                for (int kt = 0; kt < 64; kt++) {
                    int s = kt & 7;
                    uint32_t ah[4] = {H[s].x, H[s].y, H[s].z, H[s].w};
                    float* a0 = acc[kt & 1][0];
                    float* a1 = acc[kt & 1][1];
                    {
                        int c = nh * 16 + g;
                        uint2 bf = *(const uint2*)(Whs + c * WS_PITCH + kt * 8 + tg * 2);
                        uint32_t bh[2] = {bf.x, bf.y};
                        mma16816h(a0, ah, bh);
                    }
                    {
                        int c = nh * 16 + 8 + g;
                        uint2 bf = *(const uint2*)(Whs + c * WS_PITCH + kt * 8 + tg * 2);
                        uint32_t bh[2] = {bf.x, bf.y};
                        mma16816h(a1, ah, bh);
                    }
                    if (kt + 8 < 64) H[s] = *(const uint4*)(ab + (kt + 8) * 512);
                }
            }

            // wait for producers' xw[t]
            BAR_SYNC(BFULL0 + (t & 1), 384);
            const float* xb = xwb + (t & 1) * XWB_SIZE;
            float4 x0 = *(const float4*)(xb + r0 * XWB_STRIDE + (nh * 4 + tg) * 4);
            float4 x1 = *(const float4*)(xb + r1 * XWB_STRIDE + (nh * 4 + tg) * 4);
            BAR_ARRIVE(BEMPTY0 + (t & 1), 384);   // buffer consumed

            // in-register activations
            float hn[2], cn[2];
            #pragma unroll
            for (int rr = 0; rr < 2; rr++) {
                float xi = rr ? x1.x : x0.x;
                float xf = rr ? x1.y : x0.y;
                float xG = rr ? x1.z : x0.z;
                float xo = rr ? x1.w : x0.w;
                float gi = acc[0][0][2 * rr + 0] + acc[1][0][2 * rr + 0] + xi;
                float gf = acc[0][0][2 * rr + 1] + acc[1][0][2 * rr + 1] + xf;
                float gg = acc[0][1][2 * rr + 0] + acc[1][1][2 * rr + 0] + xG;
                float go = acc[0][1][2 * rr + 1] + acc[1][1][2 * rr + 1] + xo;
                float iv = 1.f / (1.f + expf(-gi));
                float fv = 1.f / (1.f + expf(-gf));
                float gv = tanhf(gg);
                float ov = 1.f / (1.f + expf(-go));
                float c_ = fv * creg[rr] + iv * gv;
                float h_ = ov * tanhf(c_);
                creg[rr] = c_;
                cn[rr] = c_; hn[rr] = h_;
            }

            // publish h fragments: pair j (even tg) with j+1 (odd tg)
            {
                uint32_t packed = pack2h(__float2half(hn[0]), __float2half(hn[1]));
                uint32_t nb = __shfl_xor_sync(0xffffffffu, packed, 1);
                if ((tg & 1) == 0) {
                    uint32_t f0 = (packed & 0xffffu) | (nb << 16);       // row r0
                    uint32_t f1 = (packed >> 16) | (nb & 0xffff0000u);   // row r1
                    int kk = j & 15, kt = j >> 4;
                    int fl = g * 4 + ((kk >> 1) & 3);
                    int rg0 = (kk >> 3) << 1;
                    size_t fb = (size_t)t * 32768 + (size_t)kt * 512 + mt * 128 + fl * 4 + rg0;
                    *(uint2*)(g_hfrag + fb) = make_uint2(f0, f1);
                }
            }

            // rec-warps barrier, then single release (v7-proven handoff)
            BAR_SYNC(BREC, 256);
            if (tid == 0) flag_release_add(g_flags + t);

            // off-critical-path output stores
            float* hdst = out + (size_t)t * BATCH * HID;
            hdst[(size_t)r0 * HID + j] = hn[0];
            hdst[(size_t)r1 * HID + j] = hn[1];
            if (t == T_STEPS - 1 && write_tail) {
                size_t base = (size_t)T_STEPS * BATCH * HID;
                out[base + (size_t)r0 * HID + j] = hn[0];
                out[base + (size_t)r1 * HID + j] = hn[1];
                out[base + BATCH * HID + (size_t)r0 * HID + j] = cn[0];
                out[base + BATCH * HID + (size_t)r1 * HID + j] = cn[1];
            }
        }
    } else {
        // ================== XW PRODUCER WARPS ==================
        const int pmt = warp - 8;        // 16 batch rows
        const int r0  = pmt * 16 + g;
        const int r1  = pmt * 16 + g + 8;

        float4 bias4[2];
        #pragma unroll
        for (int nh = 0; nh < 2; nh++) {
            int j = j0 + nh * 4 + tg;
            bias4[nh] = make_float4(b[j], b[HID + j], b[2 * HID + j], b[3 * HID + j]);
        }

        for (int t = 0; t < T_STEPS; t++) {
            if (t >= 2) BAR_SYNC(BEMPTY0 + (t & 1), 384);

            const uint32_t* ab = g_xfrag + (size_t)t * 32768 + pmt * 128 + lane * 4;
            uint4 H[8];
            #pragma unroll
            for (int q = 0; q < 8; q++) H[q] = *(const uint4*)(ab + q * 512);

            float acc[4][4];
            #pragma unroll
            for (int q = 0; q < 4; q++)
                #pragma unroll
                for (int c2 = 0; c2 < 4; c2++) acc[q][c2] = 0.f;

            #pragma unroll 8
            for (int kt = 0; kt < 64; kt++) {
                int s = kt & 7;
                uint32_t ah[4] = {H[s].x, H[s].y, H[s].z, H[s].w};
                #pragma unroll
                for (int q = 0; q < 4; q++) {
                    int c = q * 8 + g;
                    uint2 bf = *(const uint2*)(Wxs + c * WS_PITCH + kt * 8 + tg * 2);
                    uint32_t bh[2] = {bf.x, bf.y};
                    mma16816h(acc[q], ah, bh);
                }
                if (kt + 8 < 64) H[s] = *(const uint4*)(ab + (kt + 8) * 512);
            }

            float* xb = xwb + (t & 1) * XWB_SIZE;
            #pragma unroll
            for (int nh = 0; nh < 2; nh++) {
                float4 v0 = make_float4(acc[2*nh][0] + bias4[nh].x,
                                        acc[2*nh][1] + bias4[nh].y,
                                        acc[2*nh+1][0] + bias4[nh].z,
                                        acc[2*nh+1][1] + bias4[nh].w);
                float4 v1 = make_float4(acc[2*nh][2] + bias4[nh].x,
                                        acc[2*nh][3] + bias4[nh].y,
                                        acc[2*nh+1][2] + bias4[nh].z,
                                        acc[2*nh+1][3] + bias4[nh].w);
                *(float4*)(xb + r0 * XWB_STRIDE + (nh * 4 + tg) * 4) = v0;
                *(float4*)(xb + r1 * XWB_STRIDE + (nh * 4 + tg) * 4) = v1;
            }
            BAR_ARRIVE(BFULL0 + (t & 1), 384);
        }
    }
}

// =====================================================================
extern "C" void kernel_launch(void* const* d_in, const int* in_sizes, int n_in,
                              void* d_out, int out_size)
{
    const float* x  = (const float*)d_in[0];   // [512,64,1024]
    const float* Wx = (const float*)d_in[1];   // [1024,4096]
    const float* Wh = (const float*)d_in[2];   // [1024,4096]
    const float* b  = (const float*)d_in[3];   // [4096]
    float* out = (float*)d_out;

    convert_x_kernel<<<dim3(64, T_STEPS), 128>>>(x);

    const int smemB = 2 * (32 * WS_PITCH * 4) + 2 * XWB_SIZE * 4;  // 133120 + 18432
    cudaFuncSetAttribute(lstm_fused_kernel,
                         cudaFuncAttributeMaxDynamicSharedMemorySize, smemB);
    int write_tail = (out_size > T_STEPS * BATCH * HID) ? 1 : 0;
    lstm_fused_kernel<<<NCTA, 384, smemB>>>(Wx, Wh, b, out, write_tail);
}

// round 14
// speedup vs baseline: 1.3784x; 1.0454x over previous
#include <cuda_runtime.h>
#include <cuda_fp16.h>
#include <cstdint>
#include <math.h>

#define T_STEPS 512
#define BATCH   64
#define IN_DIM  1024
#define HID     1024
#define GATES   4096
#define NCTA    128

// ---------------- static scratch ----------------
__device__ uint32_t g_xfrag[(size_t)T_STEPS * 32768];   // 64 MB: x fp16, mma A-frag layout
__device__ uint32_t g_hfrag[(size_t)T_STEPS * 32768];   // 64 MB: h fp16, mma A-frag layout
__device__ int      g_flags[T_STEPS];

// ---------------- helpers ----------------
__device__ __forceinline__ uint32_t pack2h(__half a, __half b) {
    __half2 t = __halves2half2(a, b);
    return *reinterpret_cast<uint32_t*>(&t);
}
__device__ __forceinline__ void mma16816h(float* c, const uint32_t* a, const uint32_t* b) {
    asm volatile(
        "mma.sync.aligned.m16n8k16.row.col.f32.f16.f16.f32 "
        "{%0,%1,%2,%3}, {%4,%5,%6,%7}, {%8,%9}, {%0,%1,%2,%3};\n"
        : "+f"(c[0]), "+f"(c[1]), "+f"(c[2]), "+f"(c[3])
        : "r"(a[0]), "r"(a[1]), "r"(a[2]), "r"(a[3]), "r"(b[0]), "r"(b[1]));
}
__device__ __forceinline__ void flag_release_add(int* p) {
    asm volatile("red.release.gpu.global.add.s32 [%0], %1;" :: "l"(p), "r"(1) : "memory");
}
__device__ __forceinline__ int flag_acquire_ld(const int* p) {
    int v;
    asm volatile("ld.acquire.gpu.global.s32 %0, [%1];" : "=r"(v) : "l"(p) : "memory");
    return v;
}
#define BAR_SYNC(id, cnt)   asm volatile("bar.sync %0, %1;"   :: "r"(id), "r"(cnt) : "memory")
#define BAR_ARRIVE(id, cnt) asm volatile("bar.arrive %0, %1;" :: "r"(id), "r"(cnt) : "memory")
#define BFULL0  1
#define BEMPTY0 3
#define BREC    5

// =====================================================================
// Converter: x fp32 -> fp16 mma A-fragment layout.
// =====================================================================
__global__ __launch_bounds__(128)
void convert_x_kernel(const float* __restrict__ X)
{
    if (blockIdx.x == 0 && blockIdx.y == 0) {
        #pragma unroll
        for (int i = 0; i < 4; i++) g_flags[threadIdx.x + 128 * i] = 0;
    }
    const int kt = blockIdx.x;
    const int t  = blockIdx.y;
    const int mt = threadIdx.x >> 5;
    const int fl = threadIdx.x & 31;
    const int g  = fl >> 2;
    const int tg = fl & 3;
    const int bb = mt * 16 + g;
    const int k  = kt * 16 + tg * 2;

    const float* xt = X + (size_t)t * BATCH * IN_DIM;
    float2 r00 = *(const float2*)(xt + (size_t)bb * IN_DIM + k);
    float2 r10 = *(const float2*)(xt + (size_t)(bb + 8) * IN_DIM + k);
    float2 r01 = *(const float2*)(xt + (size_t)bb * IN_DIM + k + 8);
    float2 r11 = *(const float2*)(xt + (size_t)(bb + 8) * IN_DIM + k + 8);
    uint4 o;
    o.x = pack2h(__float2half(r00.x), __float2half(r00.y));
    o.y = pack2h(__float2half(r10.x), __float2half(r10.y));
    o.z = pack2h(__float2half(r01.x), __float2half(r01.y));
    o.w = pack2h(__float2half(r11.x), __float2half(r11.y));
    *(uint4*)(g_xfrag + (size_t)t * 32768 + kt * 512 + mt * 128 + fl * 4) = o;
}

// =====================================================================
// Fused persistent LSTM: 384 threads.
//   warps 0-7  : recurrence (mt = w&3, nh = w>>2, full K)
//   warps 8-11 : xw producers, warp = (mh = pw&1: 2 m-tiles, kh = pw>>1:
//                half-K), all 32 gate cols -> B-frag reused for 2 mma.
// xw handoff: SMEM ping-pong, 2 kh-halves per slot, consumed at TOP of
// each rec step (before the h spin).
// =====================================================================
#define WS_PITCH 520      // u32 per W column (520 % 32 == 8 -> conflict-free)
#define XWB_STRIDE 36     // floats per row
#define XWB_SIZE  (64 * XWB_STRIDE)   // one kh-half

__global__ __launch_bounds__(384, 1)
void lstm_fused_kernel(const float* __restrict__ Wx,
                       const float* __restrict__ Wh,
                       const float* __restrict__ b,
                       float* __restrict__ out,
                       int write_tail)
{
    extern __shared__ char smraw[];
    uint32_t* Whs  = (uint32_t*)smraw;                  // 66560 B
    uint32_t* Wxs  = Whs + 32 * WS_PITCH;               // 66560 B
    float*    xwb  = (float*)(Wxs + 32 * WS_PITCH);     // 4 * 2304 floats = 36864 B

    const int tid  = threadIdx.x;
    const int lane = tid & 31;
    const int warp = tid >> 5;
    const int g    = lane >> 2;
    const int tg   = lane & 3;
    const int j0   = blockIdx.x * 8;

    // ---- one-time: Wh & Wx slices -> SMEM fragment layout (reordered cols:
    // c: nh=c>>4, q=(c>>3)&1, cc=c&7; gate=2q+(cc&1), jj=nh*4+(cc>>1)) ----
    for (int i = tid; i < 32 * 1024; i += 384) {
        int c = i & 31;
        int k = i >> 5;
        int nhc = c >> 4, qc = (c >> 3) & 1, cc = c & 7;
        int gate = 2 * qc + (cc & 1);
        int jj   = nhc * 4 + (cc >> 1);
        size_t src = (size_t)k * GATES + gate * HID + j0 + jj;
        int kt = k >> 4, t4 = (k >> 1) & 3, w = (k >> 3) & 1, hf = k & 1;
        int word = c * WS_PITCH + kt * 8 + t4 * 2 + w;
        ((__half*)Whs)[word * 2 + hf] = __float2half(Wh[src]);
        ((__half*)Wxs)[word * 2 + hf] = __float2half(Wx[src]);
    }
    __syncthreads();

    if (warp < 8) {
        // ================== RECURRENCE WARPS ==================
        const int mt = warp & 3;
        const int nh = warp >> 2;
        const int wm = mt * 16;
        const int r0 = wm + g;
        const int r1 = wm + g + 8;
        const int j  = j0 + nh * 4 + tg;
        const int cc4 = (nh * 4 + tg) * 4;

        // bias in registers (loaded once)
        float breg[4] = { b[j], b[HID + j], b[2 * HID + j], b[3 * HID + j] };

        float creg[2] = {0.f, 0.f};

        for (int t = 0; t < T_STEPS; t++) {
            // ---- consume xw[t] at TOP of step (before the h spin) ----
            BAR_SYNC(BFULL0 + (t & 1), 384);
            const float* xb = xwb + (t & 1) * 2 * XWB_SIZE;
            float4 p00 = *(const float4*)(xb + r0 * XWB_STRIDE + cc4);
            float4 p01 = *(const float4*)(xb + XWB_SIZE + r0 * XWB_STRIDE + cc4);
            float4 p10 = *(const float4*)(xb + r1 * XWB_STRIDE + cc4);
            float4 p11 = *(const float4*)(xb + XWB_SIZE + r1 * XWB_STRIDE + cc4);
            BAR_ARRIVE(BEMPTY0 + (t & 1), 384);
            float4 x0 = make_float4(p00.x + p01.x + breg[0], p00.y + p01.y + breg[1],
                                    p00.z + p01.z + breg[2], p00.w + p01.w + breg[3]);
            float4 x1 = make_float4(p10.x + p11.x + breg[0], p10.y + p11.y + breg[1],
                                    p10.z + p11.z + breg[2], p10.w + p11.w + breg[3]);

            float acc[2][2][4];
            #pragma unroll
            for (int pp = 0; pp < 2; pp++)
                #pragma unroll
                for (int q = 0; q < 2; q++)
                    #pragma unroll
                    for (int c2 = 0; c2 < 4; c2++) acc[pp][q][c2] = 0.f;

            if (t > 0) {
                if (lane == 0) {
                    while (flag_acquire_ld(g_flags + (t - 1)) != NCTA) { }
                }
                __syncwarp();

                const uint32_t* ab = g_hfrag + (size_t)(t - 1) * 32768
                                     + mt * 128 + lane * 4;
                uint4 H[8];
                #pragma unroll
                for (int q = 0; q < 8; q++) H[q] = *(const uint4*)(ab + q * 512);

                #pragma unroll 8
                for (int kt = 0; kt < 64; kt++) {
                    int s = kt & 7;
                    uint32_t ah[4] = {H[s].x, H[s].y, H[s].z, H[s].w};
                    float* a0 = acc[kt & 1][0];
                    float* a1 = acc[kt & 1][1];
                    {
                        int c = nh * 16 + g;
                        uint2 bf = *(const uint2*)(Whs + c * WS_PITCH + kt * 8 + tg * 2);
                        uint32_t bh[2] = {bf.x, bf.y};
                        mma16816h(a0, ah, bh);
                    }
                    {
                        int c = nh * 16 + 8 + g;
                        uint2 bf = *(const uint2*)(Whs + c * WS_PITCH + kt * 8 + tg * 2);
                        uint32_t bh[2] = {bf.x, bf.y};
                        mma16816h(a1, ah, bh);
                    }
                    if (kt + 8 < 64) H[s] = *(const uint4*)(ab + (kt + 8) * 512);
                }
            }

            // ---- in-register activations ----
            float hn[2], cn[2];
            #pragma unroll
            for (int rr = 0; rr < 2; rr++) {
                float xi = rr ? x1.x : x0.x;
                float xf = rr ? x1.y : x0.y;
                float xG = rr ? x1.z : x0.z;
                float xo = rr ? x1.w : x0.w;
                float gi = acc[0][0][2 * rr + 0] + acc[1][0][2 * rr + 0] + xi;
                float gf = acc[0][0][2 * rr + 1] + acc[1][0][2 * rr + 1] + xf;
                float gg = acc[0][1][2 * rr + 0] + acc[1][1][2 * rr + 0] + xG;
                float go = acc[0][1][2 * rr + 1] + acc[1][1][2 * rr + 1] + xo;
                float iv = 1.f / (1.f + expf(-gi));
                float fv = 1.f / (1.f + expf(-gf));
                float gv = tanhf(gg);
                float ov = 1.f / (1.f + expf(-go));
                float c_ = fv * creg[rr] + iv * gv;
                float h_ = ov * tanhf(c_);
                creg[rr] = c_;
                cn[rr] = c_; hn[rr] = h_;
            }

            // ---- publish h fragments ----
            {
                uint32_t packed = pack2h(__float2half(hn[0]), __float2half(hn[1]));
                uint32_t nb = __shfl_xor_sync(0xffffffffu, packed, 1);
                if ((tg & 1) == 0) {
                    uint32_t f0 = (packed & 0xffffu) | (nb << 16);       // row r0
                    uint32_t f1 = (packed >> 16) | (nb & 0xffff0000u);   // row r1
                    int kk = j & 15, kt = j >> 4;
                    int fl = g * 4 + ((kk >> 1) & 3);
                    int rg0 = (kk >> 3) << 1;
                    size_t fb = (size_t)t * 32768 + (size_t)kt * 512 + mt * 128 + fl * 4 + rg0;
                    *(uint2*)(g_hfrag + fb) = make_uint2(f0, f1);
                }
            }

            BAR_SYNC(BREC, 256);
            if (tid == 0) flag_release_add(g_flags + t);

            // ---- off-critical-path output stores ----
            float* hdst = out + (size_t)t * BATCH * HID;
            hdst[(size_t)r0 * HID + j] = hn[0];
            hdst[(size_t)r1 * HID + j] = hn[1];
            if (t == T_STEPS - 1 && write_tail) {
                size_t base = (size_t)T_STEPS * BATCH * HID;
                out[base + (size_t)r0 * HID + j] = hn[0];
                out[base + (size_t)r1 * HID + j] = hn[1];
                out[base + BATCH * HID + (size_t)r0 * HID + j] = cn[0];
                out[base + BATCH * HID + (size_t)r1 * HID + j] = cn[1];
            }
        }
    } else {
        // ================== XW PRODUCER WARPS ==================
        // warp = (mh: m-tiles {2mh, 2mh+1}, kh: kt half); all 32 cols.
        const int pw = warp - 8;
        const int mh = pw & 1;
        const int kh = pw >> 1;

        for (int t = 0; t < T_STEPS; t++) {
            if (t >= 2) BAR_SYNC(BEMPTY0 + (t & 1), 384);

            const uint32_t* abA = g_xfrag + (size_t)t * 32768
                                  + (size_t)(kh * 32) * 512 + (2 * mh) * 128 + lane * 4;
            const uint32_t* abB = abA + 128;   // m-tile 2mh+1

            uint4 HA[4], HB[4];
            #pragma unroll
            for (int q = 0; q < 4; q++) {
                HA[q] = *(const uint4*)(abA + q * 512);
                HB[q] = *(const uint4*)(abB + q * 512);
            }

            float acc[2][4][4];
            #pragma unroll
            for (int m2 = 0; m2 < 2; m2++)
                #pragma unroll
                for (int q = 0; q < 4; q++)
                    #pragma unroll
                    for (int c2 = 0; c2 < 4; c2++) acc[m2][q][c2] = 0.f;

            #pragma unroll 4
            for (int kt2 = 0; kt2 < 32; kt2++) {
                int s = kt2 & 3;
                int ktg = kh * 32 + kt2;
                uint32_t ahA[4] = {HA[s].x, HA[s].y, HA[s].z, HA[s].w};
                uint32_t ahB[4] = {HB[s].x, HB[s].y, HB[s].z, HB[s].w};
                #pragma unroll
                for (int ct = 0; ct < 4; ct++) {
                    uint2 bf = *(const uint2*)(Wxs + (ct * 8 + g) * WS_PITCH + ktg * 8 + tg * 2);
                    uint32_t bh[2] = {bf.x, bf.y};
                    mma16816h(acc[0][ct], ahA, bh);   // B reused for both m-tiles
                    mma16816h(acc[1][ct], ahB, bh);
                }
                if (kt2 + 4 < 32) {
                    HA[s] = *(const uint4*)(abA + (kt2 + 4) * 512);
                    HB[s] = *(const uint4*)(abB + (kt2 + 4) * 512);
                }
            }

            // write raw partials into kh-half of slot (t&1)
            float* xb = xwb + ((t & 1) * 2 + kh) * XWB_SIZE;
            #pragma unroll
            for (int m2 = 0; m2 < 2; m2++) {
                int rb = mh * 32 + m2 * 16 + g;
                #pragma unroll
                for (int nh2 = 0; nh2 < 2; nh2++) {
                    int col4 = (nh2 * 4 + tg) * 4;
                    float4 v0 = make_float4(acc[m2][nh2 * 2][0], acc[m2][nh2 * 2][1],
                                            acc[m2][nh2 * 2 + 1][0], acc[m2][nh2 * 2 + 1][1]);
                    float4 v1 = make_float4(acc[m2][nh2 * 2][2], acc[m2][nh2 * 2][3],
                                            acc[m2][nh2 * 2 + 1][2], acc[m2][nh2 * 2 + 1][3]);
                    *(float4*)(xb + rb * XWB_STRIDE + col4)       = v0;
                    *(float4*)(xb + (rb + 8) * XWB_STRIDE + col4) = v1;
                }
            }
            BAR_ARRIVE(BFULL0 + (t & 1), 384);
        }
    }
}

// =====================================================================
extern "C" void kernel_launch(void* const* d_in, const int* in_sizes, int n_in,
                              void* d_out, int out_size)
{
    const float* x  = (const float*)d_in[0];   // [512,64,1024]
    const float* Wx = (const float*)d_in[1];   // [1024,4096]
    const float* Wh = (const float*)d_in[2];   // [1024,4096]
    const float* b  = (const float*)d_in[3];   // [4096]
    float* out = (float*)d_out;

    convert_x_kernel<<<dim3(64, T_STEPS), 128>>>(x);

    const int smemB = 2 * (32 * WS_PITCH * 4) + 4 * XWB_SIZE * 4;  // 133120 + 36864
    cudaFuncSetAttribute(lstm_fused_kernel,
                         cudaFuncAttributeMaxDynamicSharedMemorySize, smemB);
    int write_tail = (out_size > T_STEPS * BATCH * HID) ? 1 : 0;
    lstm_fused_kernel<<<NCTA, 384, smemB>>>(Wx, Wh, b, out, write_tail);
}